// round 8
// baseline (speedup 1.0000x reference)
#include <cuda_runtime.h>
#include <cstdint>

// CRF loss: mean_b( logZ_b - gold_b )
// Forward recurrence in LINEAR space, one warp per batch, lane = state.
//   e_t[n] = (expM @ e_{t-1})[n] * exp(emit_t[n]) * 2^{-k_t},   off += k_t
// k_t from e_{t-1}[0]'s float exponent (read during the gather, folded into
// the emission factor -> renorm costs ~0 critical-path cycles, exact in 'off').
// Dot: e broadcast via per-warp smem buffer; all chain smem ops are ordered
// volatile asm on a CONVERGED warp -> no __syncwarp on the serial path.
// Gold score folded into the same loop. Final mean fused via last-block reduce.

#define KSTATES   32
#define START_IDX 30
#define STOP_IDX  31
#define FULLMASK  0xffffffffu
#define LN2       0.6931471805599453f

__device__ float    g_scratch[4096];
__device__ unsigned g_count;          // zero-initialized; reset by last block

// s[lane] = sum_p expM[lane][p] * e[p], packed f32x2 partial (lo+hi = sum).
__device__ __forceinline__ unsigned long long crf_dot_packed(
    const unsigned long long* __restrict__ Mp, unsigned eaddr)
{
    unsigned long long ev[16];
#pragma unroll
    for (int q = 0; q < 8; q++) {
        asm volatile("ld.shared.v2.u64 {%0,%1}, [%2];"
                     : "=l"(ev[2 * q]), "=l"(ev[2 * q + 1])
                     : "r"(eaddr + 16u * q));
    }
    unsigned long long a0 = 0ull, a1 = 0ull, a2 = 0ull, a3 = 0ull;
#pragma unroll
    for (int i = 0; i < 16; i += 4) {
        asm("fma.rn.f32x2 %0, %1, %2, %0;" : "+l"(a0) : "l"(Mp[i    ]), "l"(ev[i    ]));
        asm("fma.rn.f32x2 %0, %1, %2, %0;" : "+l"(a1) : "l"(Mp[i + 1]), "l"(ev[i + 1]));
        asm("fma.rn.f32x2 %0, %1, %2, %0;" : "+l"(a2) : "l"(Mp[i + 2]), "l"(ev[i + 2]));
        asm("fma.rn.f32x2 %0, %1, %2, %0;" : "+l"(a3) : "l"(Mp[i + 3]), "l"(ev[i + 3]));
    }
    unsigned long long s01, s23, s;
    asm("add.rn.f32x2 %0, %1, %2;" : "=l"(s01) : "l"(a0),  "l"(a1));
    asm("add.rn.f32x2 %0, %1, %2;" : "=l"(s23) : "l"(a2),  "l"(a3));
    asm("add.rn.f32x2 %0, %1, %2;" : "=l"(s)   : "l"(s01), "l"(s23));
    return s;
}

// One recurrence step: read e_{t-1} from smem, return e_t (caller stores it).
__device__ __forceinline__ float crf_step(const unsigned long long* __restrict__ Mp,
                                          unsigned eaddr, float emit, int& off)
{
    float c;
    asm volatile("ld.shared.f32 %0, [%1];" : "=f"(c) : "r"(eaddr));
    int ie = (int)((__float_as_uint(c) >> 23) & 0xFF);
    if (ie == 0) ie = 127;                       // guard c==0/denormal -> r=1
    off += ie - 127;
    float r = __uint_as_float((unsigned)(254 - ie) << 23);   // 2^-(ie-127)
    float expE = __expf(emit) * r;
    unsigned long long eE2;
    asm("mov.b64 %0, {%1, %1};" : "=l"(eE2) : "f"(expE));

    unsigned long long s = crf_dot_packed(Mp, eaddr);
    unsigned long long p;
    asm("mul.rn.f32x2 %0, %1, %2;" : "=l"(p) : "l"(s), "l"(eE2));
    float lo, hi;
    asm("mov.b64 {%0, %1}, %2;" : "=f"(lo), "=f"(hi) : "l"(p));
    return lo + hi;
}

// Ordered volatile store of this lane's e (no syncwarp: converged warp,
// in-order per-warp smem pipeline, all chain smem ops are volatile asm).
__device__ __forceinline__ void crf_store_e(unsigned eaddr, int lane, float e)
{
    asm volatile("st.shared.f32 [%0], %1;"
                 :: "r"(eaddr + 4u * (unsigned)lane), "f"(e) : "memory");
}

__global__ void __launch_bounds__(128)
crf_fused_kernel(const float* __restrict__ feats,
                 const float* __restrict__ trans,
                 const int*   __restrict__ tags,
                 const int*   __restrict__ lens,
                 float* __restrict__ out,
                 int B, int T)
{
    __shared__ __align__(16) float sh_e[4][KSTATES];
    __shared__ float sh_trans[KSTATES * KSTATES];
    __shared__ float sh_red[128];
    __shared__ unsigned sh_last;

    const int tid  = threadIdx.x;
    const int wid  = tid >> 5;
    const int lane = tid & 31;

    for (int i = tid; i < KSTATES * KSTATES; i += 128)
        sh_trans[i] = trans[i];
    __syncthreads();

    const int b = blockIdx.x * 4 + wid;
    const bool active = (b < B);

    if (active) {
        const unsigned eaddr = (unsigned)__cvta_generic_to_shared(&sh_e[wid][0]);

        // Packed expM row: Mp[q] = (expM[lane][2q], expM[lane][2q+1]).
        // exp(-10000) -> exactly 0, so constraint rows/cols are free.
        unsigned long long Mp[16];
#pragma unroll
        for (int q = 0; q < 16; q++) {
            float m0 = __expf(sh_trans[lane * KSTATES + 2 * q]);
            float m1 = __expf(sh_trans[lane * KSTATES + 2 * q + 1]);
            asm("mov.b64 %0, {%1, %2};" : "=l"(Mp[q]) : "f"(m0), "f"(m1));
        }

        const int len = lens[b];
        const float* fb = feats + (size_t)b * T * KSTATES + lane;
        const int*   tb = tags  + (size_t)b * T;

        crf_store_e(eaddr, lane, (lane == START_IDX) ? 1.0f : 0.0f);

        int   off    = 0;
        float g_emit = 0.0f, g_tr = 0.0f;
        int   tprev  = START_IDX;
        float e;

        // 8-deep prefetch of emissions + tags (covers DRAM ~577cyc).
        float fbuf[8]; int tbuf[8];
#pragma unroll
        for (int i = 0; i < 8; i++) {
            bool v  = (i < len);
            fbuf[i] = v ? fb[(size_t)i * KSTATES] : 0.0f;
            tbuf[i] = v ? tb[i] : 0;
        }

        const int len8 = len & ~7;
        for (int t0 = 0; t0 < len8; t0 += 8) {
            float fn[8]; int tn[8];
#pragma unroll
            for (int i = 0; i < 8; i++) {
                int  tt = t0 + 8 + i;
                bool v  = (tt < len);
                fn[i] = v ? fb[(size_t)tt * KSTATES] : 0.0f;
                tn[i] = v ? tb[tt] : 0;
            }
#pragma unroll
            for (int j = 0; j < 8; j++) {              // branch-free body
                e = crf_step(Mp, eaddr, fbuf[j], off);
                crf_store_e(eaddr, lane, e);
                // gold score: independent, issues in the chain's stall shadow
                int tg = tbuf[j];
                g_emit += (lane == tg) ? fbuf[j] : 0.0f;
                g_tr   += sh_trans[tg * KSTATES + tprev];
                tprev = tg;
                fbuf[j] = fn[j];
                tbuf[j] = tn[j];
            }
        }
        for (int t = len8; t < len; t++) {             // <=7 step tail
            int i = t - len8;
            e = crf_step(Mp, eaddr, fbuf[i], off);
            crf_store_e(eaddr, lane, e);
            int tg = tbuf[i];
            g_emit += (lane == tg) ? fbuf[i] : 0.0f;
            g_tr   += sh_trans[tg * KSTATES + tprev];
            tprev = tg;
        }

        g_tr += sh_trans[STOP_IDX * KSTATES + tprev];

        // forward_score = off*ln2 + log( (expM @ e_final)[STOP] ) with pending renorm
        float c;
        asm volatile("ld.shared.f32 %0, [%1];" : "=f"(c) : "r"(eaddr));
        int ie = (int)((__float_as_uint(c) >> 23) & 0xFF);
        if (ie == 0) ie = 127;
        off += ie - 127;
        float r = __uint_as_float((unsigned)(254 - ie) << 23);

        unsigned long long s = crf_dot_packed(Mp, eaddr);
        float lo, hi;
        asm("mov.b64 {%0, %1}, %2;" : "=f"(lo), "=f"(hi) : "l"(s));
        float sfin  = (lo + hi) * r;
        float sstop = __shfl_sync(FULLMASK, sfin, STOP_IDX);
        float fwd   = (float)off * LN2 + __logf(sstop);

#pragma unroll
        for (int d = 16; d; d >>= 1)
            g_emit += __shfl_xor_sync(FULLMASK, g_emit, d);

        if (lane == 0)
            g_scratch[b] = fwd - g_tr - g_emit;
    }

    // ---- fused mean: last block to finish reduces g_scratch deterministically ----
    __syncthreads();
    if (tid == 0) {
        __threadfence();
        unsigned old = atomicAdd(&g_count, 1u);
        sh_last = (old == gridDim.x - 1) ? 1u : 0u;
    }
    __syncthreads();
    if (sh_last) {
        __threadfence();                 // acquire other blocks' g_scratch writes
        float v = 0.0f;
        for (int i = tid; i < B; i += 128)   // fixed order -> deterministic
            v += g_scratch[i];
        sh_red[tid] = v;
        __syncthreads();
#pragma unroll
        for (int sft = 64; sft > 0; sft >>= 1) {
            if (tid < sft) sh_red[tid] += sh_red[tid + sft];
            __syncthreads();
        }
        if (tid == 0) {
            out[0] = sh_red[0] / (float)B;
            g_count = 0;                 // reset for next graph replay
        }
    }
}

extern "C" void kernel_launch(void* const* d_in, const int* in_sizes, int n_in,
                              void* d_out, int out_size)
{
    const float* feats = (const float*)d_in[0];   // [B,T,K] f32
    const float* trans = (const float*)d_in[1];   // [K,K]   f32
    const int*   tags  = (const int*)  d_in[2];   // [B,T]   i32
    const int*   lens  = (const int*)  d_in[3];   // [B]     i32

    int B = in_sizes[3];
    int T = in_sizes[2] / B;

    int blocks = (B + 3) / 4;   // 4 warps/block -> 1 warp per SMSP
    crf_fused_kernel<<<blocks, 128>>>(feats, trans, tags, lens, (float*)d_out, B, T);
}

// round 9
// speedup vs baseline: 1.2960x; 1.2960x over previous
#include <cuda_runtime.h>
#include <cstdint>

// CRF loss: mean_b( logZ_b - gold_b )
// Forward recurrence in LINEAR space, one warp per batch, lane = state.
//   e_t[n] = (expM @ e_{t-1})[n] * exp(emit_t[n]) * 2^{-k},  off += k
// Chain is pure register/shuffle: 30 SHFL broadcasts + 30 FMA (4 chains).
// No smem on the serial path, no inline asm (ptxas schedules freely).
// t=0 peeled (closed form from START column) -> columns START/STOP drop out.
// Renorm every 4 steps (compile-time), exact via integer 'off'.
// Gold score folded in. Mean fused via last-block reduction.

#define KSTATES   32
#define START_IDX 30
#define STOP_IDX  31
#define FULLMASK  0xffffffffu
#define LN2       0.6931471805599453f

__device__ float    g_scratch[4096];
__device__ unsigned g_count;          // zero-init; reset by last block

// 30-wide dot: s[lane] = sum_{p=0..29} M[p] * e[p]  (e broadcast via shfl)
__device__ __forceinline__ float crf_dot30(const float* __restrict__ M, float e)
{
    float a0 = 0.f, a1 = 0.f, a2 = 0.f, a3 = 0.f;
#pragma unroll
    for (int p = 0; p < 28; p += 4) {
        a0 = fmaf(M[p    ], __shfl_sync(FULLMASK, e, p    ), a0);
        a1 = fmaf(M[p + 1], __shfl_sync(FULLMASK, e, p + 1), a1);
        a2 = fmaf(M[p + 2], __shfl_sync(FULLMASK, e, p + 2), a2);
        a3 = fmaf(M[p + 3], __shfl_sync(FULLMASK, e, p + 3), a3);
    }
    a0 = fmaf(M[28], __shfl_sync(FULLMASK, e, 28), a0);
    a1 = fmaf(M[29], __shfl_sync(FULLMASK, e, 29), a1);
    return (a0 + a1) + (a2 + a3);
}

// Renormalizer from e[0]'s exponent: returns 2^-(k), accumulates k into off.
__device__ __forceinline__ float crf_renorm(float e, int& off)
{
    float c  = __shfl_sync(FULLMASK, e, 0);
    int   ie = (int)((__float_as_uint(c) >> 23) & 0xFF);
    ie = (ie == 0) ? 127 : ie;                 // guard c==0/denormal
    off += ie - 127;
    return __uint_as_float((unsigned)(254 - ie) << 23);
}

__global__ void __launch_bounds__(128)
crf_fused_kernel(const float* __restrict__ feats,
                 const float* __restrict__ trans,
                 const int*   __restrict__ tags,
                 const int*   __restrict__ lens,
                 float* __restrict__ out,
                 int B, int T)
{
    __shared__ float sh_trans[KSTATES * KSTATES];
    __shared__ float sh_red[128];
    __shared__ unsigned sh_last;

    const int tid  = threadIdx.x;
    const int wid  = tid >> 5;
    const int lane = tid & 31;

    for (int i = tid; i < KSTATES * KSTATES; i += 128)
        sh_trans[i] = trans[i];
    __syncthreads();

    const int b = blockIdx.x * 4 + wid;
    if (b < B) {
        // Per-lane row of exp(transitions). exp(-10000) -> exactly 0,
        // so the structural constraints are free.
        float M[KSTATES];
#pragma unroll
        for (int p = 0; p < KSTATES; p++)
            M[p] = __expf(sh_trans[lane * KSTATES + p]);

        const int len = lens[b];
        const float* fb = feats + (size_t)b * T * KSTATES + lane;
        const int*   tb = tags  + (size_t)b * T;

        // ---- t = 0 peeled: e[n] = expM[n][START] * exp(emit0[n]) ----
        float f0   = fb[0];
        int   tag0 = tb[0];
        float e    = M[START_IDX] * __expf(f0);
        int   off  = 0;
        float g_emit = (lane == tag0) ? f0 : 0.0f;
        float g_tr   = sh_trans[tag0 * KSTATES + START_IDX];
        int   tprev  = tag0;

        // ---- steps t = 1 .. len-1, 8-unrolled, 8-deep prefetch ----
        const int steps = len - 1;
        float fbuf[8]; int tbuf[8];
#pragma unroll
        for (int i = 0; i < 8; i++) {
            int  tt = 1 + i;
            bool v  = (tt < len);
            fbuf[i] = v ? fb[(size_t)tt * KSTATES] : 0.0f;
            tbuf[i] = v ? tb[tt] : 0;
        }

        const int s8 = steps & ~7;
        for (int s0 = 0; s0 < s8; s0 += 8) {
            float fn[8]; int tn[8];
#pragma unroll
            for (int i = 0; i < 8; i++) {
                int  tt = 1 + s0 + 8 + i;
                bool v  = (tt < len);
                fn[i] = v ? fb[(size_t)tt * KSTATES] : 0.0f;
                tn[i] = v ? tb[tt] : 0;
            }
#pragma unroll
            for (int j = 0; j < 8; j++) {          // branch-free body
                float h = __expf(fbuf[j]);         // off-path (prefetched emit)
                if ((j & 3) == 0)                  // renorm every 4 steps
                    h *= crf_renorm(e, off);
                float s = crf_dot30(M, e);
                e = s * h;
                // gold score: independent, issues in the chain's stall shadow
                int tg = tbuf[j];
                g_emit += (lane == tg) ? fbuf[j] : 0.0f;
                g_tr   += sh_trans[tg * KSTATES + tprev];
                tprev = tg;
                fbuf[j] = fn[j];
                tbuf[j] = tn[j];
            }
        }
        for (int s = s8; s < steps; s++) {         // <=7 step tail
            int i = s - s8;
            float h = __expf(fbuf[i]) * crf_renorm(e, off);
            float sv = crf_dot30(M, e);
            e = sv * h;
            int tg = tbuf[i];
            g_emit += (lane == tg) ? fbuf[i] : 0.0f;
            g_tr   += sh_trans[tg * KSTATES + tprev];
            tprev = tg;
        }

        g_tr += sh_trans[STOP_IDX * KSTATES + tprev];

        // forward_score = off*ln2 + log( (expM @ e)[STOP] ); pending renorm is in off
        float sfin  = crf_dot30(M, e);                     // lane 31 = STOP row
        float sstop = __shfl_sync(FULLMASK, sfin, STOP_IDX);
        float fwd   = (float)off * LN2 + __logf(sstop);

#pragma unroll
        for (int d = 16; d; d >>= 1)
            g_emit += __shfl_xor_sync(FULLMASK, g_emit, d);

        if (lane == 0)
            g_scratch[b] = fwd - g_tr - g_emit;
    }

    // ---- fused mean: last block reduces g_scratch deterministically ----
    __syncthreads();
    if (tid == 0) {
        __threadfence();
        unsigned old = atomicAdd(&g_count, 1u);
        sh_last = (old == gridDim.x - 1) ? 1u : 0u;
    }
    __syncthreads();
    if (sh_last) {
        __threadfence();
        float v = 0.0f;
        for (int i = tid; i < B; i += 128)     // fixed order -> deterministic
            v += g_scratch[i];
        sh_red[tid] = v;
        __syncthreads();
#pragma unroll
        for (int sft = 64; sft > 0; sft >>= 1) {
            if (tid < sft) sh_red[tid] += sh_red[tid + sft];
            __syncthreads();
        }
        if (tid == 0) {
            out[0] = sh_red[0] / (float)B;
            g_count = 0;                       // reset for next graph replay
        }
    }
}

extern "C" void kernel_launch(void* const* d_in, const int* in_sizes, int n_in,
                              void* d_out, int out_size)
{
    const float* feats = (const float*)d_in[0];   // [B,T,K] f32
    const float* trans = (const float*)d_in[1];   // [K,K]   f32
    const int*   tags  = (const int*)  d_in[2];   // [B,T]   i32
    const int*   lens  = (const int*)  d_in[3];   // [B]     i32

    int B = in_sizes[3];
    int T = in_sizes[2] / B;

    int blocks = (B + 3) / 4;   // 4 warps/block -> ~1 warp per SMSP
    crf_fused_kernel<<<blocks, 128>>>(feats, trans, tags, lens, (float*)d_out, B, T);
}

// round 11
// speedup vs baseline: 1.3790x; 1.0640x over previous
#include <cuda_runtime.h>
#include <cstdint>

// CRF loss: mean_b( logZ_b - gold_b )
// Forward recurrence in LINEAR space, one warp per batch, lane = state.
//   e_t[n] = (expM @ e_{t-1})[n] * exp(emit_t[n]) * 2^{-k},  off += k
// e exchanged via per-warp smem buffer: 1 STS + 8x LDS(v2.u64) per step,
// ordered by asm-volatile (NO memory clobber, NO syncwarp -> ptxas free to
// schedule off-path work into the latency shadow). 15 packed f32x2 FMAs
// (p=0..29; pair (e30,e31) is structurally zero). Renorm every 4 steps via
// SHFL of the register copy (off the smem path). Gold score computed by a
// separate embarrassingly-parallel kernel. Mean fused via last-block reduce.

#define KSTATES   32
#define START_IDX 30
#define STOP_IDX  31
#define FULLMASK  0xffffffffu
#define LN2       0.6931471805599453f

__device__ float    g_fwd[4096];
__device__ float    g_gold[4096];
__device__ unsigned g_count;          // zero-init; reset by last block

// s[lane] = sum_{p=0..29} expM[lane][p] * e[p], e gathered from smem.
// Loads are asm volatile (ordered vs the e-store), math is plain asm.
__device__ __forceinline__ float crf_dot_smem(const unsigned long long* __restrict__ Mp,
                                              unsigned eaddr)
{
    unsigned long long ev[16];
#pragma unroll
    for (int q = 0; q < 8; q++) {
        asm volatile("ld.shared.v2.u64 {%0,%1}, [%2];"
                     : "=l"(ev[2 * q]), "=l"(ev[2 * q + 1])
                     : "r"(eaddr + 16u * q));
    }
    unsigned long long a0 = 0ull, a1 = 0ull, a2 = 0ull, a3 = 0ull;
#pragma unroll
    for (int i = 0; i < 12; i += 4) {
        asm("fma.rn.f32x2 %0, %1, %2, %0;" : "+l"(a0) : "l"(Mp[i    ]), "l"(ev[i    ]));
        asm("fma.rn.f32x2 %0, %1, %2, %0;" : "+l"(a1) : "l"(Mp[i + 1]), "l"(ev[i + 1]));
        asm("fma.rn.f32x2 %0, %1, %2, %0;" : "+l"(a2) : "l"(Mp[i + 2]), "l"(ev[i + 2]));
        asm("fma.rn.f32x2 %0, %1, %2, %0;" : "+l"(a3) : "l"(Mp[i + 3]), "l"(ev[i + 3]));
    }
    asm("fma.rn.f32x2 %0, %1, %2, %0;" : "+l"(a0) : "l"(Mp[12]), "l"(ev[12]));
    asm("fma.rn.f32x2 %0, %1, %2, %0;" : "+l"(a1) : "l"(Mp[13]), "l"(ev[13]));
    asm("fma.rn.f32x2 %0, %1, %2, %0;" : "+l"(a2) : "l"(Mp[14]), "l"(ev[14]));

    unsigned long long s01, s2;
    asm("add.rn.f32x2 %0, %1, %2;" : "=l"(s01) : "l"(a0),  "l"(a1));
    asm("add.rn.f32x2 %0, %1, %2;" : "=l"(s2)  : "l"(a2),  "l"(s01));
    asm("add.rn.f32x2 %0, %1, %2;" : "=l"(s2)  : "l"(a3),  "l"(s2));
    float lo, hi;
    asm("mov.b64 {%0, %1}, %2;" : "=f"(lo), "=f"(hi) : "l"(s2));
    return lo + hi;
}

__device__ __forceinline__ void crf_store_e(unsigned eaddr, int lane, float e)
{
    asm volatile("st.shared.f32 [%0], %1;"
                 :: "r"(eaddr + 4u * (unsigned)lane), "f"(e));
}

// 2^-k from e[0]'s exponent (register copy via shfl), k accumulated into off.
__device__ __forceinline__ float crf_renorm(float e, int& off)
{
    float c  = __shfl_sync(FULLMASK, e, 0);
    int   ie = (int)((__float_as_uint(c) >> 23) & 0xFF);
    ie = (ie == 0) ? 127 : ie;
    off += ie - 127;
    return __uint_as_float((unsigned)(254 - ie) << 23);
}

__global__ void __launch_bounds__(32)
crf_forward_kernel(const float* __restrict__ feats,
                   const float* __restrict__ trans,
                   const int*   __restrict__ lens,
                   float* __restrict__ out,
                   int B, int T)
{
    __shared__ __align__(16) float sh_e[KSTATES];

    const int lane = threadIdx.x & 31;
    const int b    = blockIdx.x;
    const unsigned eaddr = (unsigned)__cvta_generic_to_shared(sh_e);

    // Packed expM row: Mp[q] = (expM[lane][2q], expM[lane][2q+1]), q=0..14.
    // exp(-10000) -> exactly 0 (row START, column STOP), constraints free.
    unsigned long long Mp[15];
#pragma unroll
    for (int q = 0; q < 15; q++) {
        float m0 = __expf(trans[lane * KSTATES + 2 * q]);
        float m1 = __expf(trans[lane * KSTATES + 2 * q + 1]);
        asm("mov.b64 %0, {%1, %2};" : "=l"(Mp[q]) : "f"(m0), "f"(m1));
    }

    const int len = lens[b];
    const float* fb = feats + (size_t)b * T * KSTATES + lane;

    // ---- t = 0 peeled: e[n] = exp(trans[n][START] + emit0[n]) ----
    float e   = __expf(trans[lane * KSTATES + START_IDX] + fb[0]);
    int   off = 0;
    crf_store_e(eaddr, lane, e);

    // ---- steps t = 1 .. len-1; 8-unrolled, in-place 8-deep prefetch ----
    const int steps = len - 1;
    float fbuf[8];
#pragma unroll
    for (int i = 0; i < 8; i++)
        fbuf[i] = (1 + i < len) ? fb[(size_t)(1 + i) * KSTATES] : 0.0f;

    const int s8 = steps & ~7;
    for (int s0 = 0; s0 < s8; s0 += 8) {
#pragma unroll
        for (int j = 0; j < 8; j++) {
            float h = __expf(fbuf[j]);             // MUFU, off the smem path
            if ((j & 3) == 0)
                h *= crf_renorm(e, off);           // shfl overlaps the gather
            float s = crf_dot_smem(Mp, eaddr);
            e = s * h;
            crf_store_e(eaddr, lane, e);
            int tt = 9 + s0 + j;                   // reload slot for step j+8
            fbuf[j] = (tt < len) ? fb[(size_t)tt * KSTATES] : 0.0f;
        }
    }
    for (int s = s8; s < steps; s++) {             // <=7 step tail
        float h = __expf(fbuf[s - s8]) * crf_renorm(e, off);
        float sv = crf_dot_smem(Mp, eaddr);
        e = sv * h;
        crf_store_e(eaddr, lane, e);
    }

    // forward_score = off*ln2 + log( (expM @ e)[STOP] ); pending renorm in off
    float sfin  = crf_dot_smem(Mp, eaddr);         // lane 31 = STOP row
    float sstop = __shfl_sync(FULLMASK, sfin, STOP_IDX);
    if (lane == 0)
        g_fwd[b] = (float)off * LN2 + __logf(sstop);

    // ---- fused mean: last block reduces (fwd - gold) deterministically ----
    __shared__ unsigned sh_last;
    __syncthreads();
    if (lane == 0) {
        __threadfence();
        unsigned old = atomicAdd(&g_count, 1u);
        sh_last = (old == gridDim.x - 1) ? 1u : 0u;
    }
    __syncthreads();
    if (sh_last) {
        __threadfence();
        float v = 0.0f;
        for (int i = lane; i < B; i += 32)         // fixed order -> deterministic
            v += g_fwd[i] - g_gold[i];
#pragma unroll
        for (int d = 16; d; d >>= 1)
            v += __shfl_xor_sync(FULLMASK, v, d);
        if (lane == 0) {
            out[0] = v / (float)B;
            g_count = 0;                           // reset for next graph replay
        }
    }
}

// Gold score: embarrassingly parallel. One warp per batch, lanes stride t.
__global__ void __launch_bounds__(128)
crf_gold_kernel(const float* __restrict__ feats,
                const float* __restrict__ trans,
                const int*   __restrict__ tags,
                const int*   __restrict__ lens,
                int B, int T)
{
    __shared__ float sh_trans[KSTATES * KSTATES];
    const int tid  = threadIdx.x;
    const int wid  = tid >> 5;
    const int lane = tid & 31;

    for (int i = tid; i < KSTATES * KSTATES; i += 128)
        sh_trans[i] = trans[i];
    __syncthreads();

    const int b = blockIdx.x * 4 + wid;
    if (b >= B) return;

    const int* tb = tags + (size_t)b * T;
    const float* fbase = feats + (size_t)b * T * KSTATES;
    const int len = lens[b];

    float g = 0.0f;
    for (int t = lane; t < len; t += 32) {
        int tg    = tb[t];
        int tprev = (t == 0) ? START_IDX : tb[t - 1];
        g += fbase[(size_t)t * KSTATES + tg] + sh_trans[tg * KSTATES + tprev];
    }
#pragma unroll
    for (int d = 16; d; d >>= 1)
        g += __shfl_xor_sync(FULLMASK, g, d);
    if (lane == 0)
        g_gold[b] = g + sh_trans[STOP_IDX * KSTATES + tb[len - 1]];
}

extern "C" void kernel_launch(void* const* d_in, const int* in_sizes, int n_in,
                              void* d_out, int out_size)
{
    const float* feats = (const float*)d_in[0];   // [B,T,K] f32
    const float* trans = (const float*)d_in[1];   // [K,K]   f32
    const int*   tags  = (const int*)  d_in[2];   // [B,T]   i32
    const int*   lens  = (const int*)  d_in[3];   // [B]     i32

    int B = in_sizes[3];
    int T = in_sizes[2] / B;

    crf_gold_kernel<<<(B + 3) / 4, 128>>>(feats, trans, tags, lens, B, T);
    crf_forward_kernel<<<B, 32>>>(feats, trans, lens, (float*)d_out, B, T);
}